// round 6
// baseline (speedup 1.0000x reference)
#include <cuda_runtime.h>
#include <cuda_fp16.h>
#include <cstdint>

#define N_NODES 200000
#define K1      500
#define EMB     128
#define HID     64
#define NCLS    7
#define BM      64
#define NCHUNK  16
#define THREADS 256

// byte strides (conflict-free for ldmatrix wavefronts)
#define A_STRB  80      // A tile row: 32 halves (64B) + 16B pad
#define B_STRB  80
#define E_STRB  272     // emb / W1 row: 128 halves (256B) + 16B pad
#define H_STRW  68      // h fp32 row stride (words)

// smem layout (bytes)
#define OFF_BEMB 0
#define OFF_BRT1 512
#define OFF_BRT2 768
#define OFF_W2   832
#define OFF_A0   2688
#define OFF_A1   (OFF_A0 + 64*A_STRB)     // +5120
#define OFF_B0   (OFF_A1 + 64*A_STRB)     // +5120
#define OFF_B1   (OFF_B0 + 128*B_STRB)    // +10240
#define OFF_E    OFF_A0                    // overlay on A/B (dead after stage 1)
#define OFF_W1   (OFF_B1 + 128*B_STRB)
#define SMEM_BYTES (OFF_W1 + 64*E_STRB)   // 50816

// prep-packed weights, K-major [n][k], halves packed in u32 pairs
__device__ uint32_t g_WembT[EMB * 256];   // [n][kk], kk=256 (512 halves, zero-padded)
__device__ uint32_t g_W1T[HID * 64];      // [n][kk], kk=64

__device__ __forceinline__ uint32_t pack2(float a, float b) {
    __half2 h = __floats2half2_rn(a, b);
    return *reinterpret_cast<uint32_t*>(&h);
}
__device__ __forceinline__ void cp16(uint32_t dst, const void* src) {
    asm volatile("cp.async.cg.shared.global [%0], [%1], 16;"
                 :: "r"(dst), "l"(src));
}
__device__ __forceinline__ void ldsm4(uint32_t& r0, uint32_t& r1, uint32_t& r2,
                                      uint32_t& r3, uint32_t addr) {
    asm volatile("ldmatrix.sync.aligned.m8n8.x4.shared.b16 {%0,%1,%2,%3}, [%4];"
                 : "=r"(r0), "=r"(r1), "=r"(r2), "=r"(r3) : "r"(addr));
}
__device__ __forceinline__ void mma16(float c[4], const uint32_t a[4], const uint32_t b[2]) {
    asm volatile(
        "mma.sync.aligned.m16n8k16.row.col.f32.f16.f16.f32 "
        "{%0,%1,%2,%3},{%4,%5,%6,%7},{%8,%9},{%0,%1,%2,%3};"
        : "+f"(c[0]), "+f"(c[1]), "+f"(c[2]), "+f"(c[3])
        : "r"(a[0]), "r"(a[1]), "r"(a[2]), "r"(a[3]), "r"(b[0]), "r"(b[1]));
}

// ---------------- prep: K-major packed weights ----------------
__global__ void prep_kernel(const float* __restrict__ W_emb,
                            const float* __restrict__ W_rt1) {
    int i = blockIdx.x * blockDim.x + threadIdx.x;
    const int T1 = EMB * 256;
    if (i < T1) {
        int n = i >> 8, kk = i & 255;
        float w0 = (2 * kk     < K1) ? W_emb[(size_t)(2 * kk) * EMB + n]     : 0.0f;
        float w1 = (2 * kk + 1 < K1) ? W_emb[(size_t)(2 * kk + 1) * EMB + n] : 0.0f;
        g_WembT[i] = pack2(w0, w1);
    } else if (i < T1 + HID * 64) {
        int j = i - T1; int n = j >> 6, kk = j & 63;
        g_W1T[j] = pack2(W_rt1[(2 * kk) * HID + n], W_rt1[(2 * kk + 1) * HID + n]);
    }
}

// ---------------- main fused kernel ----------------
__global__ void __launch_bounds__(THREADS, 3)
policy_occ_kernel(const float* __restrict__ features,
                  const float* __restrict__ b_emb,
                  const float* __restrict__ b_rt1,
                  const float* __restrict__ b_rt2,
                  const float* __restrict__ W_rt2,
                  float* __restrict__ out)
{
    extern __shared__ char smem[];
    const int tid  = threadIdx.x;
    const int warp = tid >> 5, lane = tid & 31;
    const int grp  = lane >> 2, tig = lane & 3;
    const int wm   = (warp >> 2) * 32;        // 2 m-groups: rows 0/32
    const int wn   = (warp & 3) * 32;         // 4 n-groups: 32 cols each
    const int row0 = blockIdx.x * BM;
    const uint32_t sbase = (uint32_t)__cvta_generic_to_shared(smem);

    float*    bemb_s = (float*)(smem + OFF_BEMB);
    float*    brt1_s = (float*)(smem + OFF_BRT1);
    float*    brt2_s = (float*)(smem + OFF_BRT2);
    float*    w2_s   = (float*)(smem + OFF_W2);

    for (int i = tid; i < EMB;        i += THREADS) bemb_s[i] = b_emb[i];
    for (int i = tid; i < HID;        i += THREADS) brt1_s[i] = b_rt1[i];
    for (int i = tid; i < NCLS;       i += THREADS) brt2_s[i] = b_rt2[i];
    for (int i = tid; i < HID * NCLS; i += THREADS) w2_s[i]   = W_rt2[i];

    // W1T -> smem: 64 rows x 256B (stride 272B) = 1024 x 16B segments
    #pragma unroll
    for (int i = 0; i < 4; i++) {
        int v = tid + i * THREADS;            // 0..1023
        int r = v >> 4, seg = v & 15;
        cp16(sbase + OFF_W1 + (uint32_t)(r * E_STRB + seg * 16),
             g_W1T + r * 64 + seg * 4);
    }

    auto ldgA = [&](int c, uint4* pf) {
        #pragma unroll
        for (int i = 0; i < 2; i++) {
            int v = tid + i * THREADS;        // 0..511
            int r = v >> 3, k4 = (v & 7) * 4;
            int gr = row0 + r, gk = c * 32 + k4;
            bool p = (gr < N_NODES) && (gk + 4 <= K1);
            if (p) pf[i] = *(const uint4*)(features + (size_t)gr * K1 + gk);
            else   pf[i] = make_uint4(0, 0, 0, 0);
        }
    };
    auto stsA = [&](const uint4* pf, uint32_t offA) {
        #pragma unroll
        for (int i = 0; i < 2; i++) {
            int v = tid + i * THREADS;
            int r = v >> 3, k2 = (v & 7) * 2;
            uint2 w;
            w.x = pack2(__uint_as_float(pf[i].x), __uint_as_float(pf[i].y));
            w.y = pack2(__uint_as_float(pf[i].z), __uint_as_float(pf[i].w));
            *(uint2*)(smem + offA + r * A_STRB + k2 * 4) = w;
        }
    };
    auto cpB = [&](int c, uint32_t offB) {
        #pragma unroll
        for (int i = 0; i < 2; i++) {
            int v = tid + i * THREADS;        // 0..511: 128 rows x 4 segs
            int r = v >> 2, seg = (v & 3) * 16;
            cp16(sbase + offB + (uint32_t)(r * B_STRB + seg),
                 g_WembT + r * 256 + c * 16 + (v & 3) * 4);
        }
    };

    // -------- prologue --------
    cpB(0, OFF_B0);
    asm volatile("cp.async.commit_group;");
    uint4 pf[2];
    ldgA(0, pf);
    stsA(pf, OFF_A0);
    ldgA(1, pf);
    asm volatile("cp.async.wait_group 0;");
    __syncthreads();

    float acc[2][4][4];
    #pragma unroll
    for (int mt = 0; mt < 2; mt++)
        #pragma unroll
        for (int nt = 0; nt < 4; nt++)
            #pragma unroll
            for (int e = 0; e < 4; e++) acc[mt][nt][e] = 0.0f;

    // ldmatrix lane addressing (hoisted)
    const int lane15 = lane & 15;
    const int koffB  = (lane >> 4) * 16;
    const uint32_t aAddr0 = sbase + OFF_A0 + (uint32_t)((wm + lane15) * A_STRB + koffB);
    const uint32_t bAddr0 = sbase + OFF_B0 + (uint32_t)((wn + lane15) * B_STRB + koffB);

    // -------- stage 1 main loop --------
    for (int c = 0; c < NCHUNK; c++) {
        if (c + 1 < NCHUNK) {
            stsA(pf, (c & 1) ? OFF_A0 : OFF_A1);
            if (c + 2 < NCHUNK) ldgA(c + 2, pf);
            cpB(c + 1, (c & 1) ? OFF_B0 : OFF_B1);
            asm volatile("cp.async.commit_group;");
        }

        const uint32_t aA = aAddr0 + ((c & 1) ? 5120u : 0u);
        const uint32_t bA = bAddr0 + ((c & 1) ? 10240u : 0u);
        #pragma unroll
        for (int s = 0; s < 2; s++) {
            uint32_t a[2][4], b[4][2];
            #pragma unroll
            for (int mt = 0; mt < 2; mt++)
                ldsm4(a[mt][0], a[mt][1], a[mt][2], a[mt][3],
                      aA + mt * (16 * A_STRB) + s * 32);
            ldsm4(b[0][0], b[1][0], b[0][1], b[1][1], bA + s * 32);
            ldsm4(b[2][0], b[3][0], b[2][1], b[3][1], bA + 16 * B_STRB + s * 32);
            #pragma unroll
            for (int mt = 0; mt < 2; mt++)
                #pragma unroll
                for (int nt = 0; nt < 4; nt++)
                    mma16(acc[mt][nt], a[mt], b[nt]);
        }

        if (c + 1 < NCHUNK) {
            asm volatile("cp.async.wait_group 0;");
            __syncthreads();
        }
    }
    __syncthreads();   // A/B buffers dead; E overlays them

    // -------- epilogue 1: emb = relu(acc + b_emb), [row][k] halves --------
    uint32_t* Eu = (uint32_t*)(smem + OFF_E);
    #pragma unroll
    for (int mt = 0; mt < 2; mt++) {
        #pragma unroll
        for (int nt = 0; nt < 4; nt++) {
            const int r    = wm + mt * 16 + grp;
            const int col  = wn + nt * 8 + tig * 2;
            const int colh = (wn + nt * 8) / 2 + tig;
            const float b0 = bemb_s[col], b1 = bemb_s[col + 1];
            Eu[r * 68 + colh] =
                pack2(fmaxf(acc[mt][nt][0] + b0, 0.0f), fmaxf(acc[mt][nt][1] + b1, 0.0f));
            Eu[(r + 8) * 68 + colh] =
                pack2(fmaxf(acc[mt][nt][2] + b0, 0.0f), fmaxf(acc[mt][nt][3] + b1, 0.0f));
        }
    }
    __syncthreads();

    // -------- stage 2: h = relu(emb @ W_rt1 + b_rt1) --------
    const int wn2 = (warp & 3) * 16;
    const uint32_t eAddr  = sbase + OFF_E  + (uint32_t)((wm + lane15) * E_STRB + koffB);
    const uint32_t w1Addr = sbase + OFF_W1 + (uint32_t)((wn2 + lane15) * E_STRB + koffB);

    float acc2[2][2][4];
    #pragma unroll
    for (int mt = 0; mt < 2; mt++)
        #pragma unroll
        for (int nt = 0; nt < 2; nt++)
            #pragma unroll
            for (int e = 0; e < 4; e++) acc2[mt][nt][e] = 0.0f;

    #pragma unroll
    for (int s = 0; s < 8; s++) {
        uint32_t a[2][4], b[2][2];
        #pragma unroll
        for (int mt = 0; mt < 2; mt++)
            ldsm4(a[mt][0], a[mt][1], a[mt][2], a[mt][3],
                  eAddr + mt * (16 * E_STRB) + s * 32);
        ldsm4(b[0][0], b[1][0], b[0][1], b[1][1], w1Addr + s * 32);
        #pragma unroll
        for (int mt = 0; mt < 2; mt++)
            #pragma unroll
            for (int nt = 0; nt < 2; nt++)
                mma16(acc2[mt][nt], a[mt], b[nt]);
    }
    __syncthreads();   // done reading Eu; reuse region as fp32 h

    float* hs = (float*)(smem + OFF_E);
    #pragma unroll
    for (int mt = 0; mt < 2; mt++) {
        #pragma unroll
        for (int nt = 0; nt < 2; nt++) {
            const int r   = wm + mt * 16 + grp;
            const int col = wn2 + nt * 8 + tig * 2;
            const float b0 = brt1_s[col], b1 = brt1_s[col + 1];
            *(float2*)(hs + r * H_STRW + col) =
                make_float2(fmaxf(acc2[mt][nt][0] + b0, 0.0f),
                            fmaxf(acc2[mt][nt][1] + b1, 0.0f));
            *(float2*)(hs + (r + 8) * H_STRW + col) =
                make_float2(fmaxf(acc2[mt][nt][2] + b0, 0.0f),
                            fmaxf(acc2[mt][nt][3] + b1, 0.0f));
        }
    }
    __syncthreads();

    // -------- stage 3: out = h @ W_rt2 + b_rt2 --------
    if (warp < 2) {
        const int r  = warp * 32 + lane;
        const int gr = row0 + r;
        float o[NCLS];
        #pragma unroll
        for (int cc = 0; cc < NCLS; cc++) o[cc] = brt2_s[cc];
        #pragma unroll
        for (int k4 = 0; k4 < HID; k4 += 4) {
            float4 h4 = *(const float4*)(hs + r * H_STRW + k4);
            const float hh[4] = {h4.x, h4.y, h4.z, h4.w};
            #pragma unroll
            for (int j = 0; j < 4; j++)
                #pragma unroll
                for (int cc = 0; cc < NCLS; cc++)
                    o[cc] = fmaf(hh[j], w2_s[(k4 + j) * NCLS + cc], o[cc]);
        }
        if (gr < N_NODES) {
            #pragma unroll
            for (int cc = 0; cc < NCLS; cc++)
                out[(size_t)gr * NCLS + cc] = o[cc];
        }
    }
}

extern "C" void kernel_launch(void* const* d_in, const int* in_sizes, int n_in,
                              void* d_out, int out_size) {
    // [0] adj (unused), [1] features, [2] W_emb, [3] b_emb,
    // [4] W_rt1, [5] b_rt1, [6] W_rt2, [7] b_rt2
    const float* features = (const float*)d_in[1];
    const float* W_emb    = (const float*)d_in[2];
    const float* b_emb    = (const float*)d_in[3];
    const float* W_rt1    = (const float*)d_in[4];
    const float* b_rt1    = (const float*)d_in[5];
    const float* W_rt2    = (const float*)d_in[6];
    const float* b_rt2    = (const float*)d_in[7];
    float* out = (float*)d_out;

    const int prep_elems = EMB * 256 + HID * 64;
    prep_kernel<<<(prep_elems + 255) / 256, 256>>>(W_emb, W_rt1);

    cudaFuncSetAttribute(policy_occ_kernel,
                         cudaFuncAttributeMaxDynamicSharedMemorySize, SMEM_BYTES);
    const int grid = (N_NODES + BM - 1) / BM;   // 3125 + 1 = 3126
    policy_occ_kernel<<<grid, THREADS, SMEM_BYTES>>>(
        features, b_emb, b_rt1, b_rt2, W_rt2, out);
}

// round 7
// speedup vs baseline: 1.2651x; 1.2651x over previous
#include <cuda_runtime.h>
#include <cuda_fp16.h>
#include <cstdint>

#define N_NODES 200000
#define K1      500
#define KK      256        // 512 halves (zero-padded) = 256 half2
#define EMB     128
#define HID     64
#define NCLS    7
#define BM      64
#define NCHUNK  16
#define THREADS 128

// strides in uint32 units (bank-conflict-free, verified in R3)
#define A_STR   20         // A tile row: 16 u32 + 4 pad
#define B_STR   136        // B tile row: 128 u32 + 8 pad
#define E_STR   68         // emb half2 row / h fp32 row: 64 + 4
#define W1_STR  72         // W1 row: 64 u32 + 8 pad

// byte offsets in dynamic smem
#define OFF_BEMB 0
#define OFF_BRT1 512
#define OFF_BRT2 768
#define OFF_W2   832                       // 448 floats -> ends 2624
#define OFF_A0   2688                      // 64*A_STR*4 = 5120
#define OFF_A1   (OFF_A0 + 5120)
#define OFF_B0   (OFF_A1 + 5120)           // 16*B_STR*4 = 8704
#define OFF_B1   (OFF_B0 + 8704)
#define OFF_E    OFF_A0                    // overlay: 64*E_STR*4 = 17408 <= 27648
#define OFF_W1   (OFF_B1 + 8704)           // 64*W1_STR*4 = 18432
#define SMEM_BYTES (OFF_W1 + 18432)        // 48768 -> 4 CTAs/SM

// prep-packed weights: half2 pairs along k, [kk][n] (coalesced rows)
__device__ uint32_t g_WembP[KK * EMB];     // [kk][n]
__device__ uint32_t g_W1P[(EMB/2) * HID];  // [kk][n]

__device__ __forceinline__ uint32_t pack2(float a, float b) {
    __half2 h = __floats2half2_rn(a, b);
    return *reinterpret_cast<uint32_t*>(&h);
}
__device__ __forceinline__ void cp16(uint32_t dst, const void* src) {
    asm volatile("cp.async.cg.shared.global [%0], [%1], 16;"
                 :: "r"(dst), "l"(src));
}
__device__ __forceinline__ void mma16(float c[4], const uint32_t a[4], const uint32_t b[2]) {
    asm volatile(
        "mma.sync.aligned.m16n8k16.row.col.f32.f16.f16.f32 "
        "{%0,%1,%2,%3},{%4,%5,%6,%7},{%8,%9},{%0,%1,%2,%3};"
        : "+f"(c[0]), "+f"(c[1]), "+f"(c[2]), "+f"(c[3])
        : "r"(a[0]), "r"(a[1]), "r"(a[2]), "r"(a[3]), "r"(b[0]), "r"(b[1]));
}

// ---------------- prep: pack weights as half2-k-pairs, [kk][n] ----------------
__global__ void prep_kernel(const float* __restrict__ W_emb,
                            const float* __restrict__ W_rt1) {
    int i = blockIdx.x * blockDim.x + threadIdx.x;
    const int T1 = KK * EMB;
    if (i < T1) {
        int kk = i >> 7, n = i & 127;
        float w0 = (2 * kk     < K1) ? W_emb[(size_t)(2 * kk) * EMB + n]     : 0.0f;
        float w1 = (2 * kk + 1 < K1) ? W_emb[(size_t)(2 * kk + 1) * EMB + n] : 0.0f;
        g_WembP[i] = pack2(w0, w1);
    } else if (i < T1 + (EMB/2) * HID) {
        int j = i - T1; int kk = j >> 6, n = j & 63;
        g_W1P[j] = pack2(W_rt1[(2 * kk) * HID + n], W_rt1[(2 * kk + 1) * HID + n]);
    }
}

// ---------------- main fused kernel ----------------
__global__ void __launch_bounds__(THREADS, 4)
policy_4cta_kernel(const float* __restrict__ features,
                   const float* __restrict__ b_emb,
                   const float* __restrict__ b_rt1,
                   const float* __restrict__ b_rt2,
                   const float* __restrict__ W_rt2,
                   float* __restrict__ out)
{
    extern __shared__ char smem[];
    const int tid  = threadIdx.x;
    const int warp = tid >> 5, lane = tid & 31;
    const int grp  = lane >> 2, tig = lane & 3;
    const int wm   = (warp >> 1) * 32;     // rows 0 / 32
    const int wn   = (warp & 1) * 64;      // stage-1 cols 0 / 64
    const int row0 = blockIdx.x * BM;
    const uint32_t sbase = (uint32_t)__cvta_generic_to_shared(smem);

    float*    bemb_s = (float*)(smem + OFF_BEMB);
    float*    brt1_s = (float*)(smem + OFF_BRT1);
    float*    brt2_s = (float*)(smem + OFF_BRT2);
    float*    w2_s   = (float*)(smem + OFF_W2);
    uint32_t* A0s    = (uint32_t*)(smem + OFF_A0);
    uint32_t* A1s    = (uint32_t*)(smem + OFF_A1);
    uint32_t* B0s    = (uint32_t*)(smem + OFF_B0);
    uint32_t* B1s    = (uint32_t*)(smem + OFF_B1);
    uint32_t* Eu     = (uint32_t*)(smem + OFF_E);
    uint32_t* W1s    = (uint32_t*)(smem + OFF_W1);

    for (int i = tid; i < EMB;        i += THREADS) bemb_s[i] = b_emb[i];
    for (int i = tid; i < HID;        i += THREADS) brt1_s[i] = b_rt1[i];
    for (int i = tid; i < NCLS;       i += THREADS) brt2_s[i] = b_rt2[i];
    for (int i = tid; i < HID * NCLS; i += THREADS) w2_s[i]   = W_rt2[i];

    // W1 -> smem: 64 kk-rows x 64 u32 (stride 72 u32), 1024 x 16B
    #pragma unroll
    for (int i = 0; i < 8; i++) {
        int v = tid + i * THREADS;            // 0..1023
        int kk = v >> 4, n4 = (v & 15) * 4;
        cp16(sbase + OFF_W1 + (uint32_t)((kk * W1_STR + n4) * 4),
             g_W1P + kk * HID + n4);
    }

    auto ldgA = [&](int c, uint4* pf) {
        #pragma unroll
        for (int i = 0; i < 4; i++) {
            int v = tid + i * THREADS;        // 0..511
            int r = v >> 3, k4 = (v & 7) * 4;
            int gr = row0 + r, gk = c * 32 + k4;
            bool p = (gr < N_NODES) && (gk + 4 <= K1);
            if (p) pf[i] = *(const uint4*)(features + (size_t)gr * K1 + gk);
            else   pf[i] = make_uint4(0, 0, 0, 0);
        }
    };
    auto stsA = [&](const uint4* pf, uint32_t* Ab) {
        #pragma unroll
        for (int i = 0; i < 4; i++) {
            int v = tid + i * THREADS;
            int r = v >> 3, k2 = (v & 7) * 2;
            uint2 w;
            w.x = pack2(__uint_as_float(pf[i].x), __uint_as_float(pf[i].y));
            w.y = pack2(__uint_as_float(pf[i].z), __uint_as_float(pf[i].w));
            *(uint2*)(Ab + r * A_STR + k2) = w;
        }
    };
    auto cpB = [&](int c, uint32_t offB) {
        #pragma unroll
        for (int i = 0; i < 4; i++) {
            int v = tid + i * THREADS;        // 0..511: 16 kk x 32 segs
            int kk = v >> 5, n4 = (v & 31) * 4;
            cp16(sbase + offB + (uint32_t)((kk * B_STR + n4) * 4),
                 g_WembP + (c * 16 + kk) * EMB + n4);
        }
    };

    // -------- prologue --------
    cpB(0, OFF_B0);
    asm volatile("cp.async.commit_group;");
    uint4 pf[4];
    ldgA(0, pf);
    stsA(pf, A0s);
    ldgA(1, pf);
    asm volatile("cp.async.wait_group 0;");
    __syncthreads();

    float acc[2][8][4];
    #pragma unroll
    for (int mt = 0; mt < 2; mt++)
        #pragma unroll
        for (int nt = 0; nt < 8; nt++)
            #pragma unroll
            for (int e = 0; e < 4; e++) acc[mt][nt][e] = 0.0f;

    // -------- stage 1 main loop --------
    for (int c = 0; c < NCHUNK; c++) {
        const uint32_t* Ab = (c & 1) ? A1s : A0s;
        const uint32_t* Bb = (c & 1) ? B1s : B0s;
        if (c + 1 < NCHUNK) {
            stsA(pf, (c & 1) ? A0s : A1s);
            if (c + 2 < NCHUNK) ldgA(c + 2, pf);
            cpB(c + 1, (c & 1) ? OFF_B0 : OFF_B1);
            asm volatile("cp.async.commit_group;");
        }

        #pragma unroll
        for (int s = 0; s < 2; s++) {
            uint32_t a[2][4], b[8][2];
            #pragma unroll
            for (int mt = 0; mt < 2; mt++) {
                const int r = wm + mt * 16 + grp;
                a[mt][0] = Ab[r * A_STR + s * 8 + tig];
                a[mt][1] = Ab[(r + 8) * A_STR + s * 8 + tig];
                a[mt][2] = Ab[r * A_STR + s * 8 + tig + 4];
                a[mt][3] = Ab[(r + 8) * A_STR + s * 8 + tig + 4];
            }
            #pragma unroll
            for (int nt = 0; nt < 8; nt++) {
                const int col = wn + nt * 8 + grp;
                b[nt][0] = Bb[(s * 8 + tig) * B_STR + col];
                b[nt][1] = Bb[(s * 8 + tig + 4) * B_STR + col];
            }
            #pragma unroll
            for (int mt = 0; mt < 2; mt++)
                #pragma unroll
                for (int nt = 0; nt < 8; nt++)
                    mma16(acc[mt][nt], a[mt], b[nt]);
        }

        if (c + 1 < NCHUNK) {
            asm volatile("cp.async.wait_group 0;");
            __syncthreads();
        }
    }
    __syncthreads();   // A/B buffers dead; E overlays them

    // -------- epilogue 1: emb = relu(acc + b_emb) as half2 [row][colh] --------
    #pragma unroll
    for (int mt = 0; mt < 2; mt++) {
        #pragma unroll
        for (int nt = 0; nt < 8; nt++) {
            const int r    = wm + mt * 16 + grp;
            const int col  = wn + nt * 8 + tig * 2;
            const int colh = (wn + nt * 8) / 2 + tig;
            const float b0 = bemb_s[col], b1 = bemb_s[col + 1];
            Eu[r * E_STR + colh] =
                pack2(fmaxf(acc[mt][nt][0] + b0, 0.0f), fmaxf(acc[mt][nt][1] + b1, 0.0f));
            Eu[(r + 8) * E_STR + colh] =
                pack2(fmaxf(acc[mt][nt][2] + b0, 0.0f), fmaxf(acc[mt][nt][3] + b1, 0.0f));
        }
    }
    __syncthreads();

    // -------- stage 2: h = relu(emb @ W_rt1 + b_rt1) --------
    const int wn2 = (warp & 1) * 32;
    float acc2[2][4][4];
    #pragma unroll
    for (int mt = 0; mt < 2; mt++)
        #pragma unroll
        for (int nt = 0; nt < 4; nt++)
            #pragma unroll
            for (int e = 0; e < 4; e++) acc2[mt][nt][e] = 0.0f;

    #pragma unroll
    for (int s = 0; s < 8; s++) {
        uint32_t a[2][4], b[4][2];
        #pragma unroll
        for (int mt = 0; mt < 2; mt++) {
            const int r = wm + mt * 16 + grp;
            a[mt][0] = Eu[r * E_STR + s * 8 + tig];
            a[mt][1] = Eu[(r + 8) * E_STR + s * 8 + tig];
            a[mt][2] = Eu[r * E_STR + s * 8 + tig + 4];
            a[mt][3] = Eu[(r + 8) * E_STR + s * 8 + tig + 4];
        }
        #pragma unroll
        for (int nt = 0; nt < 4; nt++) {
            const int col = wn2 + nt * 8 + grp;
            b[nt][0] = W1s[(s * 8 + tig) * W1_STR + col];
            b[nt][1] = W1s[(s * 8 + tig + 4) * W1_STR + col];
        }
        #pragma unroll
        for (int mt = 0; mt < 2; mt++)
            #pragma unroll
            for (int nt = 0; nt < 4; nt++)
                mma16(acc2[mt][nt], a[mt], b[nt]);
    }
    __syncthreads();   // done reading Eu; reuse region as fp32 h

    float* hs = (float*)(smem + OFF_E);
    #pragma unroll
    for (int mt = 0; mt < 2; mt++) {
        #pragma unroll
        for (int nt = 0; nt < 4; nt++) {
            const int r   = wm + mt * 16 + grp;
            const int col = wn2 + nt * 8 + tig * 2;
            const float b0 = brt1_s[col], b1 = brt1_s[col + 1];
            *(float2*)(hs + r * E_STR + col) =
                make_float2(fmaxf(acc2[mt][nt][0] + b0, 0.0f),
                            fmaxf(acc2[mt][nt][1] + b1, 0.0f));
            *(float2*)(hs + (r + 8) * E_STR + col) =
                make_float2(fmaxf(acc2[mt][nt][2] + b0, 0.0f),
                            fmaxf(acc2[mt][nt][3] + b1, 0.0f));
        }
    }
    __syncthreads();

    // -------- stage 3: out = h @ W_rt2 + b_rt2 --------
    if (warp < 2) {
        const int r  = warp * 32 + lane;
        const int gr = row0 + r;
        float o[NCLS];
        #pragma unroll
        for (int cc = 0; cc < NCLS; cc++) o[cc] = brt2_s[cc];
        #pragma unroll
        for (int k4 = 0; k4 < HID; k4 += 4) {
            float4 h4 = *(const float4*)(hs + r * E_STR + k4);
            const float hh[4] = {h4.x, h4.y, h4.z, h4.w};
            #pragma unroll
            for (int j = 0; j < 4; j++)
                #pragma unroll
                for (int cc = 0; cc < NCLS; cc++)
                    o[cc] = fmaf(hh[j], w2_s[(k4 + j) * NCLS + cc], o[cc]);
        }
        if (gr < N_NODES) {
            #pragma unroll
            for (int cc = 0; cc < NCLS; cc++)
                out[(size_t)gr * NCLS + cc] = o[cc];
        }
    }
}

extern "C" void kernel_launch(void* const* d_in, const int* in_sizes, int n_in,
                              void* d_out, int out_size) {
    // [0] adj (unused), [1] features, [2] W_emb, [3] b_emb,
    // [4] W_rt1, [5] b_rt1, [6] W_rt2, [7] b_rt2
    const float* features = (const float*)d_in[1];
    const float* W_emb    = (const float*)d_in[2];
    const float* b_emb    = (const float*)d_in[3];
    const float* W_rt1    = (const float*)d_in[4];
    const float* b_rt1    = (const float*)d_in[5];
    const float* W_rt2    = (const float*)d_in[6];
    const float* b_rt2    = (const float*)d_in[7];
    float* out = (float*)d_out;

    const int prep_elems = KK * EMB + (EMB / 2) * HID;
    prep_kernel<<<(prep_elems + 255) / 256, 256>>>(W_emb, W_rt1);

    cudaFuncSetAttribute(policy_4cta_kernel,
                         cudaFuncAttributeMaxDynamicSharedMemorySize, SMEM_BYTES);
    const int grid = (N_NODES + BM - 1) / BM;   // 3125
    policy_4cta_kernel<<<grid, THREADS, SMEM_BYTES>>>(
        features, b_emb, b_rt1, b_rt2, W_rt2, out);
}